// round 11
// baseline (speedup 1.0000x reference)
#include <cuda_runtime.h>
#include <cuda_fp16.h>
#include <cstdint>
#include <cstddef>

// ---------------- problem constants ----------------------------------------
#define B_DIM 64
#define T_DIM 1000
#define I_DIM 512                  // K
#define O_DIM 256                  // N
#define M_TOTAL (B_DIM * T_DIM)    // 64000
#define MT 64                      // CTA M tile
#define NT 128                     // CTA N tile (2 N-splits)
#define KC 64                      // K chunk (64 fp16 = 128B row)
#define NCHUNK (I_DIM / KC)        // 8
#define NBLOCKS ((M_TOTAL / MT) * (O_DIM / NT))   // 2000

#define ALPHA_C 0.95f
#define BETA_C 0.9f

// ---------------- device scratch --------------------------------------------
__device__ __align__(16) __half g_Wh[O_DIM * I_DIM];
__device__ __align__(16) __half g_h[(size_t)M_TOTAL * O_DIM];   // 32.8 MB

// ---------------- helpers ----------------------------------------------------
static __device__ __forceinline__ uint32_t smem_u32(const void* p) {
    uint32_t r;
    asm("{ .reg .u64 t; cvta.to.shared.u64 t, %1; cvt.u32.u64 %0, t; }"
        : "=r"(r) : "l"(p));
    return r;
}

// 128B-row swizzle: 16B chunk c (0..7) XORed with (row & 7).
static __device__ __forceinline__ uint32_t swz128(uint32_t row, uint32_t c) {
    return (row << 7) + ((c ^ (row & 7)) << 4);
}

static __device__ __forceinline__ void ldsm4(uint32_t* r, uint32_t addr) {
    asm volatile("ldmatrix.sync.aligned.m8n8.x4.shared.b16 {%0,%1,%2,%3}, [%4];"
                 : "=r"(r[0]), "=r"(r[1]), "=r"(r[2]), "=r"(r[3]) : "r"(addr));
}

static __device__ __forceinline__ void mma16816(float* d, const uint32_t* a,
                                                const uint32_t* b) {
    asm volatile(
        "mma.sync.aligned.m16n8k16.row.col.f32.f16.f16.f32 "
        "{%0,%1,%2,%3}, {%4,%5,%6,%7}, {%8,%9}, {%0,%1,%2,%3};"
        : "+f"(d[0]), "+f"(d[1]), "+f"(d[2]), "+f"(d[3])
        : "r"(a[0]), "r"(a[1]), "r"(a[2]), "r"(a[3]), "r"(b[0]), "r"(b[1]));
}

static __device__ __forceinline__ void cpasync16(uint32_t dst, const void* src) {
    asm volatile("cp.async.cg.shared.global [%0], [%1], 16;"
                 :: "r"(dst), "l"(src) : "memory");
}
static __device__ __forceinline__ void cpasync_commit() {
    asm volatile("cp.async.commit_group;" ::: "memory");
}
static __device__ __forceinline__ void cpasync_wait0() {
    asm volatile("cp.async.wait_group 0;" ::: "memory");
}

static __device__ __forceinline__ uint32_t packh2(float a, float b) {
    __half2 h = __floats2half2_rn(a, b);
    return *reinterpret_cast<uint32_t*>(&h);
}

// ---------------- kernel 0: convert W to fp16 (vectorized) ------------------
__global__ void convert_w_kernel(const float* __restrict__ W) {
    int i = (blockIdx.x * 256 + threadIdx.x) * 8;
    float4 v0 = *reinterpret_cast<const float4*>(&W[i]);
    float4 v1 = *reinterpret_cast<const float4*>(&W[i + 4]);
    uint4 o = make_uint4(packh2(v0.x, v0.y), packh2(v0.z, v0.w),
                         packh2(v1.x, v1.y), packh2(v1.z, v1.w));
    *reinterpret_cast<uint4*>(&g_Wh[i]) = o;
}

// ---------------- kernel 1: GEMM (MT=64, NT=128, 3 CTAs/SM) -----------------
// SMEM per stage (24576 B): A[64x128B]=8K @0, W[128x128B]=16K @8192
#define STAGE_BYTES 24576
#define SMEM_TOTAL (2 * STAGE_BYTES)
#define A_OFF 0
#define W_OFF 8192

__global__ void __launch_bounds__(256, 3) gemm_kernel(const float* __restrict__ A) {
    extern __shared__ char smem[];
    uint32_t sb = smem_u32(smem);
    const int tid = threadIdx.x;
    const int lane = tid & 31;
    const int warp = tid >> 5;
    const int wm = warp >> 2;          // 0..1 (M, 32 rows each)
    const int wn = warp & 3;           // 0..3 (N, 32 cols each)
    // adjacent bids share the same M tile -> A gets L2 reuse
    const int n0 = (blockIdx.x & 1) * NT;
    const int m0 = (blockIdx.x >> 1) * MT;

    // per-thread A load coords: 16 f32 (4 float4) per thread per chunk.
    const int a_row = tid >> 2;        // 0..63
    const int a_g   = tid & 3;
    const float* a_src_base = &A[(size_t)(m0 + a_row) * I_DIM + a_g * 16];
    const uint32_t a_sw0 = swz128((uint32_t)a_row, (uint32_t)(2 * a_g));
    const uint32_t a_sw1 = swz128((uint32_t)a_row, (uint32_t)(2 * a_g + 1));

    // ldmatrix lane geometry
    const int q  = lane >> 3;
    const int r8 = lane & 7;

    float acc[2][4][4];
    #pragma unroll
    for (int a1 = 0; a1 < 2; a1++)
        #pragma unroll
        for (int a2 = 0; a2 < 4; a2++)
            #pragma unroll
            for (int a3 = 0; a3 < 4; a3++) acc[a1][a2][a3] = 0.0f;

    float4 pa[4];

    // ---- prologue: chunk 0 -> stage 0 ----
    {
        #pragma unroll
        for (int v = 0; v < 4; v++)
            pa[v] = *reinterpret_cast<const float4*>(a_src_base + 4 * v);
        // W chunk 0: 128 rows x 128B = 1024 x 16B items, 256 threads x 4
        #pragma unroll
        for (int r = 0; r < 4; r++) {
            int e = tid + 256 * r;
            int row = e >> 3, c = e & 7;
            size_t so = (size_t)(n0 + row) * I_DIM + c * 8;
            cpasync16(sb + W_OFF + swz128((uint32_t)row, (uint32_t)c), &g_Wh[so]);
        }
        cpasync_commit();
        uint4 h0 = make_uint4(packh2(pa[0].x, pa[0].y), packh2(pa[0].z, pa[0].w),
                              packh2(pa[1].x, pa[1].y), packh2(pa[1].z, pa[1].w));
        uint4 h1 = make_uint4(packh2(pa[2].x, pa[2].y), packh2(pa[2].z, pa[2].w),
                              packh2(pa[3].x, pa[3].y), packh2(pa[3].z, pa[3].w));
        *reinterpret_cast<uint4*>(smem + A_OFF + a_sw0) = h0;
        *reinterpret_cast<uint4*>(smem + A_OFF + a_sw1) = h1;
        cpasync_wait0();
    }
    __syncthreads();

    // ---- main loop: 8 chunks ----
    #pragma unroll 1
    for (int i = 0; i < NCHUNK; i++) {
        const uint32_t st = sb + (uint32_t)(i & 1) * STAGE_BYTES;
        const bool has_next = (i + 1) < NCHUNK;
        const uint32_t nst = sb + (uint32_t)((i + 1) & 1) * STAGE_BYTES;

        if (has_next) {
            const int k0n = (i + 1) * KC;
            const float* sp = a_src_base + k0n;
            #pragma unroll
            for (int v = 0; v < 4; v++)
                pa[v] = *reinterpret_cast<const float4*>(sp + 4 * v);
            #pragma unroll
            for (int r = 0; r < 4; r++) {
                int e = tid + 256 * r;
                int row = e >> 3, c = e & 7;
                size_t so = (size_t)(n0 + row) * I_DIM + k0n + c * 8;
                cpasync16(nst + W_OFF + swz128((uint32_t)row, (uint32_t)c),
                          &g_Wh[so]);
            }
            cpasync_commit();
        }

        // ---- compute chunk i: 4 k16 sub-steps ----
        #pragma unroll
        for (int k16 = 0; k16 < 4; k16++) {
            uint32_t bfr[2][4], afr[2][4];
            #pragma unroll
            for (int nn = 0; nn < 2; nn++) {
                uint32_t nrow = (uint32_t)(wn * 32 + nn * 16 + (q >> 1) * 8 + r8);
                uint32_t c = (uint32_t)(2 * k16 + (q & 1));
                ldsm4(bfr[nn], st + W_OFF + swz128(nrow, c));
            }
            #pragma unroll
            for (int mt = 0; mt < 2; mt++) {
                uint32_t mrow = (uint32_t)(wm * 32 + mt * 16 + (q & 1) * 8 + r8);
                uint32_t c = (uint32_t)(2 * k16 + (q >> 1));
                ldsm4(afr[mt], st + A_OFF + swz128(mrow, c));
            }
            #pragma unroll
            for (int mt = 0; mt < 2; mt++)
                #pragma unroll
                for (int nt = 0; nt < 4; nt++)
                    mma16816(acc[mt][nt], afr[mt], &bfr[nt >> 1][2 * (nt & 1)]);
        }

        if (has_next) {
            uint4 h0 = make_uint4(packh2(pa[0].x, pa[0].y), packh2(pa[0].z, pa[0].w),
                                  packh2(pa[1].x, pa[1].y), packh2(pa[1].z, pa[1].w));
            uint4 h1 = make_uint4(packh2(pa[2].x, pa[2].y), packh2(pa[2].z, pa[2].w),
                                  packh2(pa[3].x, pa[3].y), packh2(pa[3].z, pa[3].w));
            uint32_t off = (uint32_t)(nst - sb);
            *reinterpret_cast<uint4*>(smem + off + A_OFF + a_sw0) = h0;
            *reinterpret_cast<uint4*>(smem + off + A_OFF + a_sw1) = h1;
            cpasync_wait0();
        }
        __syncthreads();
    }

    // ---- epilogue: acc -> g_h (fp16) ----
    #pragma unroll
    for (int mt = 0; mt < 2; mt++) {
        int m = m0 + wm * 32 + mt * 16 + (lane >> 2);
        #pragma unroll
        for (int nt = 0; nt < 4; nt++) {
            int n = n0 + wn * 32 + nt * 8 + 2 * (lane & 3);
            *reinterpret_cast<uint32_t*>(&g_h[(size_t)m * O_DIM + n]) =
                packh2(acc[mt][nt][0], acc[mt][nt][1]);
            *reinterpret_cast<uint32_t*>(&g_h[(size_t)(m + 8) * O_DIM + n]) =
                packh2(acc[mt][nt][2], acc[mt][nt][3]);
        }
    }
}

// ---------------- kernel 2: temporal scan (fp16 reads, 40-deep prefetch) ----
#define SCAN_U 40
#define SCAN_G (T_DIM / SCAN_U)   // 25

__global__ void __launch_bounds__(128) scan_kernel(float* __restrict__ out) {
    int cid = blockIdx.x * 128 + threadIdx.x;    // 0..16383
    int b = cid >> 8;
    int o = cid & 255;
    const __half* hp = g_h + (size_t)b * T_DIM * O_DIM + o;
    float* op = out + (size_t)b * T_DIM * O_DIM + o;

    float flt = 0.0f, acc = 0.0f;
    float buf[SCAN_U];
    #pragma unroll
    for (int u = 0; u < SCAN_U; u++) buf[u] = __half2float(hp[(size_t)u * O_DIM]);

    #pragma unroll 1
    for (int g = 0; g < SCAN_G; g++) {
        float nb[SCAN_U];
        if (g < SCAN_G - 1) {
            #pragma unroll
            for (int u = 0; u < SCAN_U; u++)
                nb[u] = __half2float(hp[(size_t)((g + 1) * SCAN_U + u) * O_DIM]);
        }
        #pragma unroll
        for (int u = 0; u < SCAN_U; u++) {
            float old = flt;
            flt = ALPHA_C * flt + buf[u];
            acc = BETA_C * acc + old;
            op[(size_t)(g * SCAN_U + u) * O_DIM] = acc;
        }
        if (g < SCAN_G - 1) {
            #pragma unroll
            for (int u = 0; u < SCAN_U; u++) buf[u] = nb[u];
        }
    }
}

// ---------------- launch ----------------------------------------------------
extern "C" void kernel_launch(void* const* d_in, const int* in_sizes, int n_in,
                              void* d_out, int out_size) {
    (void)in_sizes; (void)n_in; (void)out_size;
    const float* inputs = (const float*)d_in[0];
    const float* W = (const float*)d_in[1];
    float* out = (float*)d_out;

    cudaFuncSetAttribute(gemm_kernel,
                         cudaFuncAttributeMaxDynamicSharedMemorySize, SMEM_TOTAL);

    convert_w_kernel<<<(O_DIM * I_DIM) / (256 * 8), 256>>>(W);
    gemm_kernel<<<NBLOCKS, 256, SMEM_TOTAL>>>(inputs);
    scan_kernel<<<(B_DIM * O_DIM) / 128, 128>>>(out);
}

// round 12
// speedup vs baseline: 1.1250x; 1.1250x over previous
#include <cuda_runtime.h>
#include <cuda_fp16.h>
#include <cstdint>
#include <cstddef>

// ---------------- problem constants ----------------------------------------
#define B_DIM 64
#define T_DIM 1000
#define I_DIM 512                  // K
#define O_DIM 256                  // N
#define M_TOTAL (B_DIM * T_DIM)    // 64000
#define MT 64                      // CTA M tile
#define KC 64                      // K chunk (64 fp16 = 128B row)
#define NCHUNK (I_DIM / KC)        // 8
#define NBLOCKS (M_TOTAL / MT)     // 1000

#define ALPHA_C 0.95f
#define BETA_C 0.9f

// ---------------- device scratch --------------------------------------------
__device__ __align__(16) __half g_Wh[O_DIM * I_DIM];
__device__ __align__(16) __half g_h[(size_t)M_TOTAL * O_DIM];   // 32.8 MB

// ---------------- helpers ----------------------------------------------------
static __device__ __forceinline__ uint32_t smem_u32(const void* p) {
    uint32_t r;
    asm("{ .reg .u64 t; cvta.to.shared.u64 t, %1; cvt.u32.u64 %0, t; }"
        : "=r"(r) : "l"(p));
    return r;
}

// 128B-row swizzle: 16B chunk c (0..7) XORed with (row & 7).
static __device__ __forceinline__ uint32_t swz128(uint32_t row, uint32_t c) {
    return (row << 7) + ((c ^ (row & 7)) << 4);
}

static __device__ __forceinline__ void ldsm4(uint32_t* r, uint32_t addr) {
    asm volatile("ldmatrix.sync.aligned.m8n8.x4.shared.b16 {%0,%1,%2,%3}, [%4];"
                 : "=r"(r[0]), "=r"(r[1]), "=r"(r[2]), "=r"(r[3]) : "r"(addr));
}

static __device__ __forceinline__ void mma16816(float* d, const uint32_t* a,
                                                const uint32_t* b) {
    asm volatile(
        "mma.sync.aligned.m16n8k16.row.col.f32.f16.f16.f32 "
        "{%0,%1,%2,%3}, {%4,%5,%6,%7}, {%8,%9}, {%0,%1,%2,%3};"
        : "+f"(d[0]), "+f"(d[1]), "+f"(d[2]), "+f"(d[3])
        : "r"(a[0]), "r"(a[1]), "r"(a[2]), "r"(a[3]), "r"(b[0]), "r"(b[1]));
}

static __device__ __forceinline__ void cpasync16(uint32_t dst, const void* src) {
    asm volatile("cp.async.cg.shared.global [%0], [%1], 16;"
                 :: "r"(dst), "l"(src) : "memory");
}
static __device__ __forceinline__ void cpasync_commit() {
    asm volatile("cp.async.commit_group;" ::: "memory");
}
static __device__ __forceinline__ void cpasync_wait0() {
    asm volatile("cp.async.wait_group 0;" ::: "memory");
}

static __device__ __forceinline__ uint32_t packh2(float a, float b) {
    __half2 h = __floats2half2_rn(a, b);
    return *reinterpret_cast<uint32_t*>(&h);
}

// ---------------- kernel 0: convert W to fp16 (vectorized) ------------------
__global__ void convert_w_kernel(const float* __restrict__ W) {
    int i = (blockIdx.x * 256 + threadIdx.x) * 8;
    float4 v0 = *reinterpret_cast<const float4*>(&W[i]);
    float4 v1 = *reinterpret_cast<const float4*>(&W[i + 4]);
    uint4 o = make_uint4(packh2(v0.x, v0.y), packh2(v0.z, v0.w),
                         packh2(v1.x, v1.y), packh2(v1.z, v1.w));
    *reinterpret_cast<uint4*>(&g_Wh[i]) = o;
}

// ---------------- kernel 1: GEMM (MT=64, N=256, 2 CTAs/SM, low-reg) ---------
// SMEM: stage s (40960 B): A-fp16[64x128B]=8K @0, W[256x128B]=32K @8192
//       staging A-f32 (single): 64 rows x 272B pitch = 17408 B
#define STAGE_BYTES 40960
#define STG_OFF (2 * STAGE_BYTES)          // 81920
#define STG_PITCH 272
#define SMEM_TOTAL (STG_OFF + 64 * STG_PITCH)   // 99328
#define A_OFF 0
#define W_OFF 8192

__global__ void __launch_bounds__(256, 2) gemm_kernel(const float* __restrict__ A) {
    extern __shared__ char smem[];
    uint32_t sb = smem_u32(smem);
    const int tid = threadIdx.x;
    const int lane = tid & 31;
    const int warp = tid >> 5;
    const int wm = warp >> 2;          // 0..1 (M, 32 rows each)
    const int wn = warp & 3;           // 0..3 (N, 64 cols each)
    const int m0 = blockIdx.x * MT;

    // per-thread A coords: row = tid>>2 (0..63), a_g = tid&3 -> 16 f32 each
    const int a_row = tid >> 2;
    const int a_g   = tid & 3;
    const float* a_src_base = &A[(size_t)(m0 + a_row) * I_DIM + a_g * 16];
    const uint32_t a_sw0 = swz128((uint32_t)a_row, (uint32_t)(2 * a_g));
    const uint32_t a_sw1 = swz128((uint32_t)a_row, (uint32_t)(2 * a_g + 1));
    const uint32_t stg = (uint32_t)(STG_OFF + a_row * STG_PITCH + a_g * 64);

    // ldmatrix lane geometry
    const int q  = lane >> 3;
    const int r8 = lane & 7;

    float acc[2][8][4];
    #pragma unroll
    for (int a1 = 0; a1 < 2; a1++)
        #pragma unroll
        for (int a2 = 0; a2 < 8; a2++)
            #pragma unroll
            for (int a3 = 0; a3 < 4; a3++) acc[a1][a2][a3] = 0.0f;

    // ---- prologue ----
    {
        // W chunk 0 -> stage0 W  (256 rows x 128B = 2048 x 16B, 256 thr x 8)
        #pragma unroll
        for (int r = 0; r < 8; r++) {
            int e = tid + 256 * r;
            int row = e >> 3, c = e & 7;
            size_t so = (size_t)row * I_DIM + c * 8;
            cpasync16(sb + W_OFF + swz128((uint32_t)row, (uint32_t)c), &g_Wh[so]);
        }
        // A f32 chunk 1 -> staging
        #pragma unroll
        for (int j = 0; j < 4; j++)
            cpasync16(sb + stg + j * 16, a_src_base + KC + j * 4);
        cpasync_commit();

        // A chunk 0 direct LDG -> fp16 stage0 (transient regs, 8 at a time)
        {
            float4 v0 = *reinterpret_cast<const float4*>(a_src_base);
            float4 v1 = *reinterpret_cast<const float4*>(a_src_base + 4);
            *reinterpret_cast<uint4*>(smem + A_OFF + a_sw0) =
                make_uint4(packh2(v0.x, v0.y), packh2(v0.z, v0.w),
                           packh2(v1.x, v1.y), packh2(v1.z, v1.w));
            float4 v2 = *reinterpret_cast<const float4*>(a_src_base + 8);
            float4 v3 = *reinterpret_cast<const float4*>(a_src_base + 12);
            *reinterpret_cast<uint4*>(smem + A_OFF + a_sw1) =
                make_uint4(packh2(v2.x, v2.y), packh2(v2.z, v2.w),
                           packh2(v3.x, v3.y), packh2(v3.z, v3.w));
        }
        cpasync_wait0();
    }
    __syncthreads();

    // ---- main loop: 8 chunks ----
    #pragma unroll 1
    for (int i = 0; i < NCHUNK; i++) {
        const uint32_t st = sb + (uint32_t)(i & 1) * STAGE_BYTES;
        const bool has_next = (i + 1) < NCHUNK;
        const uint32_t nst = sb + (uint32_t)((i + 1) & 1) * STAGE_BYTES;

        if (has_next) {
            // 1. convert staged f32 chunk (i+1) -> fp16 into nst A.
            //    (nst A was last read before the previous barrier: safe.)
            {
                const float4* p = reinterpret_cast<const float4*>(smem + stg);
                float4 v0 = p[0], v1 = p[1];
                *reinterpret_cast<uint4*>(smem + (nst - sb) + A_OFF + a_sw0) =
                    make_uint4(packh2(v0.x, v0.y), packh2(v0.z, v0.w),
                               packh2(v1.x, v1.y), packh2(v1.z, v1.w));
                float4 v2 = p[2], v3 = p[3];
                *reinterpret_cast<uint4*>(smem + (nst - sb) + A_OFF + a_sw1) =
                    make_uint4(packh2(v2.x, v2.y), packh2(v2.z, v2.w),
                               packh2(v3.x, v3.y), packh2(v3.z, v3.w));
            }
            // 2. prefetch A f32 chunk i+2 into staging (values already in regs
            //    above, so overwrite is safe for this thread's region)
            if (i + 2 < NCHUNK) {
                const float* sp = a_src_base + (i + 2) * KC;
                #pragma unroll
                for (int j = 0; j < 4; j++)
                    cpasync16(sb + stg + j * 16, sp + j * 4);
            }
            // 3. W chunk i+1 -> nst W
            {
                const int k0n = (i + 1) * KC;
                #pragma unroll
                for (int r = 0; r < 8; r++) {
                    int e = tid + 256 * r;
                    int row = e >> 3, c = e & 7;
                    size_t so = (size_t)row * I_DIM + k0n + c * 8;
                    cpasync16(nst + W_OFF + swz128((uint32_t)row, (uint32_t)c),
                              &g_Wh[so]);
                }
            }
            cpasync_commit();
        }

        // ---- compute chunk i: 4 k16 sub-steps ----
        #pragma unroll
        for (int k16 = 0; k16 < 4; k16++) {
            uint32_t bfr[4][4], afr[2][4];
            #pragma unroll
            for (int nn = 0; nn < 4; nn++) {
                uint32_t nrow = (uint32_t)(wn * 64 + nn * 16 + (q >> 1) * 8 + r8);
                uint32_t c = (uint32_t)(2 * k16 + (q & 1));
                ldsm4(bfr[nn], st + W_OFF + swz128(nrow, c));
            }
            #pragma unroll
            for (int mt = 0; mt < 2; mt++) {
                uint32_t mrow = (uint32_t)(wm * 32 + mt * 16 + (q & 1) * 8 + r8);
                uint32_t c = (uint32_t)(2 * k16 + (q >> 1));
                ldsm4(afr[mt], st + A_OFF + swz128(mrow, c));
            }
            #pragma unroll
            for (int mt = 0; mt < 2; mt++)
                #pragma unroll
                for (int nt = 0; nt < 8; nt++)
                    mma16816(acc[mt][nt], afr[mt], &bfr[nt >> 1][2 * (nt & 1)]);
        }

        if (has_next) cpasync_wait0();
        __syncthreads();
    }

    // ---- epilogue: acc -> g_h (fp16) ----
    #pragma unroll
    for (int mt = 0; mt < 2; mt++) {
        int m = m0 + wm * 32 + mt * 16 + (lane >> 2);
        #pragma unroll
        for (int nt = 0; nt < 8; nt++) {
            int n = wn * 64 + nt * 8 + 2 * (lane & 3);
            *reinterpret_cast<uint32_t*>(&g_h[(size_t)m * O_DIM + n]) =
                packh2(acc[mt][nt][0], acc[mt][nt][1]);
            *reinterpret_cast<uint32_t*>(&g_h[(size_t)(m + 8) * O_DIM + n]) =
                packh2(acc[mt][nt][2], acc[mt][nt][3]);
        }
    }
}

// ---------------- kernel 2: temporal scan (fp16 reads, 40-deep prefetch) ----
#define SCAN_U 40
#define SCAN_G (T_DIM / SCAN_U)   // 25

__global__ void __launch_bounds__(128) scan_kernel(float* __restrict__ out) {
    int cid = blockIdx.x * 128 + threadIdx.x;    // 0..16383
    int b = cid >> 8;
    int o = cid & 255;
    const __half* hp = g_h + (size_t)b * T_DIM * O_DIM + o;
    float* op = out + (size_t)b * T_DIM * O_DIM + o;

    float flt = 0.0f, acc = 0.0f;
    float buf[SCAN_U];
    #pragma unroll
    for (int u = 0; u < SCAN_U; u++) buf[u] = __half2float(hp[(size_t)u * O_DIM]);

    #pragma unroll 1
    for (int g = 0; g < SCAN_G; g++) {
        float nb[SCAN_U];
        if (g < SCAN_G - 1) {
            #pragma unroll
            for (int u = 0; u < SCAN_U; u++)
                nb[u] = __half2float(hp[(size_t)((g + 1) * SCAN_U + u) * O_DIM]);
        }
        #pragma unroll
        for (int u = 0; u < SCAN_U; u++) {
            float old = flt;
            flt = ALPHA_C * flt + buf[u];
            acc = BETA_C * acc + old;
            op[(size_t)(g * SCAN_U + u) * O_DIM] = acc;
        }
        if (g < SCAN_G - 1) {
            #pragma unroll
            for (int u = 0; u < SCAN_U; u++) buf[u] = nb[u];
        }
    }
}

// ---------------- launch ----------------------------------------------------
extern "C" void kernel_launch(void* const* d_in, const int* in_sizes, int n_in,
                              void* d_out, int out_size) {
    (void)in_sizes; (void)n_in; (void)out_size;
    const float* inputs = (const float*)d_in[0];
    const float* W = (const float*)d_in[1];
    float* out = (float*)d_out;

    cudaFuncSetAttribute(gemm_kernel,
                         cudaFuncAttributeMaxDynamicSharedMemorySize, SMEM_TOTAL);

    convert_w_kernel<<<(O_DIM * I_DIM) / (256 * 8), 256>>>(W);
    gemm_kernel<<<NBLOCKS, 256, SMEM_TOTAL>>>(inputs);
    scan_kernel<<<(B_DIM * O_DIM) / 128, 128>>>(out);
}

// round 14
// speedup vs baseline: 1.2705x; 1.1293x over previous
#include <cuda_runtime.h>
#include <cuda_fp16.h>
#include <cstdint>
#include <cstddef>

// ---------------- problem constants ----------------------------------------
#define B_DIM 64
#define T_DIM 1000
#define I_DIM 512                  // K
#define O_DIM 256                  // N
#define M_TOTAL (B_DIM * T_DIM)    // 64000
#define MT 64                      // CTA M tile
#define KC 64                      // K chunk (64 fp16 = 128B row)
#define NCHUNK (I_DIM / KC)        // 8
#define NBLOCKS (M_TOTAL / MT)     // 1000

#define ALPHA_C 0.95f
#define BETA_C 0.9f

// ---------------- device scratch --------------------------------------------
__device__ __align__(16) __half g_Wh[O_DIM * I_DIM];
__device__ __align__(16) __half g_h[(size_t)M_TOTAL * O_DIM];   // 32.8 MB

// ---------------- helpers ----------------------------------------------------
static __device__ __forceinline__ uint32_t smem_u32(const void* p) {
    uint32_t r;
    asm("{ .reg .u64 t; cvta.to.shared.u64 t, %1; cvt.u32.u64 %0, t; }"
        : "=r"(r) : "l"(p));
    return r;
}

// 128B-row swizzle: 16B chunk c (0..7) XORed with (row & 7).
static __device__ __forceinline__ uint32_t swz128(uint32_t row, uint32_t c) {
    return (row << 7) + ((c ^ (row & 7)) << 4);
}

static __device__ __forceinline__ void ldsm4(uint32_t* r, uint32_t addr) {
    asm volatile("ldmatrix.sync.aligned.m8n8.x4.shared.b16 {%0,%1,%2,%3}, [%4];"
                 : "=r"(r[0]), "=r"(r[1]), "=r"(r[2]), "=r"(r[3]) : "r"(addr));
}

static __device__ __forceinline__ void mma16816(float* d, const uint32_t* a,
                                                const uint32_t* b) {
    asm volatile(
        "mma.sync.aligned.m16n8k16.row.col.f32.f16.f16.f32 "
        "{%0,%1,%2,%3}, {%4,%5,%6,%7}, {%8,%9}, {%0,%1,%2,%3};"
        : "+f"(d[0]), "+f"(d[1]), "+f"(d[2]), "+f"(d[3])
        : "r"(a[0]), "r"(a[1]), "r"(a[2]), "r"(a[3]), "r"(b[0]), "r"(b[1]));
}

static __device__ __forceinline__ void cpasync16(uint32_t dst, const void* src) {
    asm volatile("cp.async.cg.shared.global [%0], [%1], 16;"
                 :: "r"(dst), "l"(src) : "memory");
}
static __device__ __forceinline__ void cpasync_commit() {
    asm volatile("cp.async.commit_group;" ::: "memory");
}
static __device__ __forceinline__ void cpasync_wait0() {
    asm volatile("cp.async.wait_group 0;" ::: "memory");
}

static __device__ __forceinline__ uint32_t packh2(float a, float b) {
    __half2 h = __floats2half2_rn(a, b);
    return *reinterpret_cast<uint32_t*>(&h);
}

// ---------------- kernel 0: convert W to fp16 (vectorized) ------------------
__global__ void convert_w_kernel(const float* __restrict__ W) {
    int i = (blockIdx.x * 256 + threadIdx.x) * 8;
    float4 v0 = *reinterpret_cast<const float4*>(&W[i]);
    float4 v1 = *reinterpret_cast<const float4*>(&W[i + 4]);
    uint4 o = make_uint4(packh2(v0.x, v0.y), packh2(v0.z, v0.w),
                         packh2(v1.x, v1.y), packh2(v1.z, v1.w));
    *reinterpret_cast<uint4*>(&g_Wh[i]) = o;
}

// ---------------- kernel 1: GEMM (exact R7 winner: MT=64, 2 CTAs/SM) --------
// SMEM per stage (40960 B): A[64x128B]=8K @0, W[256x128B]=32K @8192
#define STAGE_BYTES 40960
#define SMEM_TOTAL (2 * STAGE_BYTES)
#define A_OFF 0
#define W_OFF 8192

__global__ void __launch_bounds__(256, 2) gemm_kernel(const float* __restrict__ A) {
    extern __shared__ char smem[];
    uint32_t sb = smem_u32(smem);
    const int tid = threadIdx.x;
    const int lane = tid & 31;
    const int warp = tid >> 5;
    const int wm = warp >> 2;          // 0..1 (M, 32 rows each)
    const int wn = warp & 3;           // 0..3 (N, 64 cols each)
    const int m0 = blockIdx.x * MT;

    // per-thread A load coords: 16 f32 (4 float4) per thread per chunk.
    const int a_row = tid >> 2;        // 0..63
    const int a_g   = tid & 3;
    const float* a_src_base = &A[(size_t)(m0 + a_row) * I_DIM + a_g * 16];
    const uint32_t a_sw0 = swz128((uint32_t)a_row, (uint32_t)(2 * a_g));
    const uint32_t a_sw1 = swz128((uint32_t)a_row, (uint32_t)(2 * a_g + 1));

    // ldmatrix lane geometry
    const int q  = lane >> 3;
    const int r8 = lane & 7;

    float acc[2][8][4];
    #pragma unroll
    for (int a1 = 0; a1 < 2; a1++)
        #pragma unroll
        for (int a2 = 0; a2 < 8; a2++)
            #pragma unroll
            for (int a3 = 0; a3 < 4; a3++) acc[a1][a2][a3] = 0.0f;

    float4 pa[4];

    // ---- prologue: chunk 0 -> stage 0 ----
    {
        #pragma unroll
        for (int v = 0; v < 4; v++)
            pa[v] = *reinterpret_cast<const float4*>(a_src_base + 4 * v);
        // W chunk 0: 256 rows x 128B = 2048 x 16B items, 256 threads x 8
        #pragma unroll
        for (int r = 0; r < 8; r++) {
            int e = tid + 256 * r;
            int row = e >> 3, c = e & 7;
            size_t so = (size_t)row * I_DIM + c * 8;
            cpasync16(sb + W_OFF + swz128((uint32_t)row, (uint32_t)c), &g_Wh[so]);
        }
        cpasync_commit();
        uint4 h0 = make_uint4(packh2(pa[0].x, pa[0].y), packh2(pa[0].z, pa[0].w),
                              packh2(pa[1].x, pa[1].y), packh2(pa[1].z, pa[1].w));
        uint4 h1 = make_uint4(packh2(pa[2].x, pa[2].y), packh2(pa[2].z, pa[2].w),
                              packh2(pa[3].x, pa[3].y), packh2(pa[3].z, pa[3].w));
        *reinterpret_cast<uint4*>(smem + A_OFF + a_sw0) = h0;
        *reinterpret_cast<uint4*>(smem + A_OFF + a_sw1) = h1;
        cpasync_wait0();
    }
    __syncthreads();

    // ---- main loop: 8 chunks ----
    #pragma unroll 1
    for (int i = 0; i < NCHUNK; i++) {
        const uint32_t st = sb + (uint32_t)(i & 1) * STAGE_BYTES;
        const bool has_next = (i + 1) < NCHUNK;
        const uint32_t nst = sb + (uint32_t)((i + 1) & 1) * STAGE_BYTES;

        if (has_next) {
            const int k0n = (i + 1) * KC;
            const float* sp = a_src_base + k0n;
            #pragma unroll
            for (int v = 0; v < 4; v++)
                pa[v] = *reinterpret_cast<const float4*>(sp + 4 * v);
            #pragma unroll
            for (int r = 0; r < 8; r++) {
                int e = tid + 256 * r;
                int row = e >> 3, c = e & 7;
                size_t so = (size_t)row * I_DIM + k0n + c * 8;
                cpasync16(nst + W_OFF + swz128((uint32_t)row, (uint32_t)c),
                          &g_Wh[so]);
            }
            cpasync_commit();
        }

        // ---- compute chunk i: 4 k16 sub-steps ----
        #pragma unroll
        for (int k16 = 0; k16 < 4; k16++) {
            uint32_t bfr[4][4], afr[2][4];
            #pragma unroll
            for (int nn = 0; nn < 4; nn++) {
                uint32_t nrow = (uint32_t)(wn * 64 + nn * 16 + (q >> 1) * 8 + r8);
                uint32_t c = (uint32_t)(2 * k16 + (q & 1));
                ldsm4(bfr[nn], st + W_OFF + swz128(nrow, c));
            }
            #pragma unroll
            for (int mt = 0; mt < 2; mt++) {
                uint32_t mrow = (uint32_t)(wm * 32 + mt * 16 + (q & 1) * 8 + r8);
                uint32_t c = (uint32_t)(2 * k16 + (q >> 1));
                ldsm4(afr[mt], st + A_OFF + swz128(mrow, c));
            }
            #pragma unroll
            for (int mt = 0; mt < 2; mt++)
                #pragma unroll
                for (int nt = 0; nt < 8; nt++)
                    mma16816(acc[mt][nt], afr[mt], &bfr[nt >> 1][2 * (nt & 1)]);
        }

        if (has_next) {
            uint4 h0 = make_uint4(packh2(pa[0].x, pa[0].y), packh2(pa[0].z, pa[0].w),
                                  packh2(pa[1].x, pa[1].y), packh2(pa[1].z, pa[1].w));
            uint4 h1 = make_uint4(packh2(pa[2].x, pa[2].y), packh2(pa[2].z, pa[2].w),
                                  packh2(pa[3].x, pa[3].y), packh2(pa[3].z, pa[3].w));
            uint32_t off = (uint32_t)(nst - sb);
            *reinterpret_cast<uint4*>(smem + off + A_OFF + a_sw0) = h0;
            *reinterpret_cast<uint4*>(smem + off + A_OFF + a_sw1) = h1;
            cpasync_wait0();
        }
        __syncthreads();
    }

    // ---- epilogue: acc -> g_h (fp16) ----
    #pragma unroll
    for (int mt = 0; mt < 2; mt++) {
        int m = m0 + wm * 32 + mt * 16 + (lane >> 2);
        #pragma unroll
        for (int nt = 0; nt < 8; nt++) {
            int n = wn * 64 + nt * 8 + 2 * (lane & 3);
            *reinterpret_cast<uint32_t*>(&g_h[(size_t)m * O_DIM + n]) =
                packh2(acc[mt][nt][0], acc[mt][nt][1]);
            *reinterpret_cast<uint32_t*>(&g_h[(size_t)(m + 8) * O_DIM + n]) =
                packh2(acc[mt][nt][2], acc[mt][nt][3]);
        }
    }
}

// ---------------- kernel 2: overlapped-segment parallel scan ----------------
// 4 segments of 250 outputs; segments 1..3 warm up over the preceding 200
// steps from zero state (state contraction alpha^200 ~ 3.5e-5 makes the
// dropped carry negligible). 65536 independent chains.
#define SEGS 4
#define SEG_LEN 250               // outputs per segment
#define WARM 200                  // warm-up steps (multiple of SU)
#define SU 25                     // prefetch batch

__global__ void __launch_bounds__(256) scan_kernel(float* __restrict__ out) {
    int cid = blockIdx.x * 256 + threadIdx.x;    // 0..65535
    int seg = cid >> 14;                         // 0..3
    int chain = cid & 16383;
    int b = chain >> 8;
    int o = chain & 255;
    const __half* hp = g_h + (size_t)b * T_DIM * O_DIM + o;
    float* op = out + (size_t)b * T_DIM * O_DIM + o;

    const int t0 = seg * SEG_LEN;                // first emitted t
    const int tb = (seg == 0) ? 0 : t0 - WARM;   // first processed t
    const int warmg = (t0 - tb) / SU;            // 0 or 8 warm groups
    const int ng = warmg + SEG_LEN / SU;         // 10 or 18 total groups

    float flt = 0.0f, acc = 0.0f;
    float buf[SU];
    #pragma unroll
    for (int u = 0; u < SU; u++)
        buf[u] = __half2float(hp[(size_t)(tb + u) * O_DIM]);

    #pragma unroll 1
    for (int g = 0; g < ng; g++) {
        float nb[SU];
        if (g < ng - 1) {
            int tn = tb + (g + 1) * SU;
            #pragma unroll
            for (int u = 0; u < SU; u++)
                nb[u] = __half2float(hp[(size_t)(tn + u) * O_DIM]);
        }
        if (g < warmg) {
            #pragma unroll
            for (int u = 0; u < SU; u++) {
                float old = flt;
                flt = ALPHA_C * flt + buf[u];
                acc = BETA_C * acc + old;
            }
        } else {
            int t = tb + g * SU;
            #pragma unroll
            for (int u = 0; u < SU; u++) {
                float old = flt;
                flt = ALPHA_C * flt + buf[u];
                acc = BETA_C * acc + old;
                op[(size_t)(t + u) * O_DIM] = acc;
            }
        }
        if (g < ng - 1) {
            #pragma unroll
            for (int u = 0; u < SU; u++) buf[u] = nb[u];
        }
    }
}

// ---------------- launch ----------------------------------------------------
extern "C" void kernel_launch(void* const* d_in, const int* in_sizes, int n_in,
                              void* d_out, int out_size) {
    (void)in_sizes; (void)n_in; (void)out_size;
    const float* inputs = (const float*)d_in[0];
    const float* W = (const float*)d_in[1];
    float* out = (float*)d_out;

    cudaFuncSetAttribute(gemm_kernel,
                         cudaFuncAttributeMaxDynamicSharedMemorySize, SMEM_TOTAL);

    convert_w_kernel<<<(O_DIM * I_DIM) / (256 * 8), 256>>>(W);
    gemm_kernel<<<NBLOCKS, 256, SMEM_TOTAL>>>(inputs);
    scan_kernel<<<(SEGS * B_DIM * O_DIM) / 256, 256>>>(out);
}